// round 5
// baseline (speedup 1.0000x reference)
#include <cuda_runtime.h>

// Problem shapes (fixed for this dataset entry)
#define B_   4
#define Q_   128
#define N_   50000
#define C_   20
#define BQ_  (B_ * Q_)          // 512
#define BN_  (B_ * N_)          // 200000
#define NV_  (N_ / 4)           // 12500 float4 per row
#define S_   10                 // chunks per row
#define CHUNK_ (NV_ / S_)       // 1250 float4 per chunk

#define MIN_PTS_NUM  50
#define MIN_INST_CLS 4
#define FIXSCALE 16777216.0f    // 2^24 fixed-point for deterministic sigmoid sum

// Output layout (fp32 concatenation, matching reference return order)
#define OFF_SCORES ((size_t)BQ_ * N_)            // 25,600,000
#define OFF_VALID  (OFF_SCORES + BQ_)
#define OFF_CLS    (OFF_VALID + BQ_)
#define OFF_GID    (OFF_CLS + BQ_)

// Scratch (no device allocation -> __device__ globals; zero-initialized, and
// finalize restores them to zero at the end of every invocation).
__device__ int                g_cls_pred[BQ_];
__device__ int                g_cnt[BQ_];
__device__ unsigned long long g_ssum[BQ_];
__device__ int                g_done[BQ_];

// Inline per-row argmax over C=20 class logits. All threads of the block read
// the same addresses -> uniform broadcast loads (L1/L2-hit after first block
// of the row). Matches jnp.argmax first-max semantics.
__device__ __forceinline__ int row_argmax(const float* __restrict__ p)
{
    float best = __ldg(&p[0]);
    int bi = 0;
    #pragma unroll
    for (int c = 1; c < C_; c++) {
        float v = __ldg(&p[c]);
        if (v > best) { best = v; bi = c; }
    }
    return bi;
}

// ---------------------------------------------------------------------------
// Kernel 1: grid (S_, BQ_). One block per 1250-float4 chunk of one (b,q) row.
// Computes its own class argmax inline (no prep launch). cls<4 rows are
// invalid regardless of count -> stream zeros, no logit read. Otherwise:
// sel = (logit>0) & (seg==cls)  [sigmoid(x)>0.5 <=> x>0, no MUFU for select];
// write mask (streaming), block-reduce (count, fixed-point sigmoid sum), one
// deterministic atomic pair per block.
// ---------------------------------------------------------------------------
__global__ __launch_bounds__(256)
void mask_chunk_kernel(const float* __restrict__ mask_logits,
                       const float* __restrict__ cls_logits,
                       const int* __restrict__ seg_pred,
                       float* __restrict__ out_masks,
                       float* __restrict__ out_cls)
{
    const int chunk = blockIdx.x;
    const int bq    = blockIdx.y;
    const int b     = bq >> 7;            // / Q_
    const int cls   = row_argmax(cls_logits + bq * C_);
    const size_t base = (size_t)bq * NV_ + (size_t)chunk * CHUNK_;

    if (chunk == 0 && threadIdx.x == 0) {
        g_cls_pred[bq] = cls;
        out_cls[bq] = (float)cls;
    }

    float4* __restrict__ om = reinterpret_cast<float4*>(out_masks) + base;

    if (cls < MIN_INST_CLS) {
        const float4 z = make_float4(0.f, 0.f, 0.f, 0.f);
        #pragma unroll
        for (int k = 0; k < 5; k++) {
            int i = threadIdx.x + k * 256;
            if (i < CHUNK_) __stcs(&om[i], z);
        }
        return;
    }

    const float4* __restrict__ ml = reinterpret_cast<const float4*>(mask_logits) + base;
    const int4*   __restrict__ sp = reinterpret_cast<const int4*>(seg_pred) +
                                    (size_t)b * NV_ + (size_t)chunk * CHUNK_;

    int   cnt  = 0;
    float ssum = 0.f;

    // Fully unrolled: 5 independent (float4, int4) load pairs batched up
    // front for MLP, then compute+store.
    float4 x[5]; int4 s[5]; bool ok[5];
    #pragma unroll
    for (int k = 0; k < 5; k++) {
        int i = threadIdx.x + k * 256;
        ok[k] = (i < CHUNK_);
        if (ok[k]) { x[k] = __ldcs(&ml[i]); s[k] = __ldg(&sp[i]); }
    }
    #pragma unroll
    for (int k = 0; k < 5; k++) {
        if (!ok[k]) continue;
        int i = threadIdx.x + k * 256;
        bool s0 = (x[k].x > 0.f) & (s[k].x == cls);
        bool s1 = (x[k].y > 0.f) & (s[k].y == cls);
        bool s2 = (x[k].z > 0.f) & (s[k].z == cls);
        bool s3 = (x[k].w > 0.f) & (s[k].w == cls);
        float4 o;
        o.x = s0 ? 1.f : 0.f;
        o.y = s1 ? 1.f : 0.f;
        o.z = s2 ? 1.f : 0.f;
        o.w = s3 ? 1.f : 0.f;
        __stcs(&om[i], o);
        cnt += (int)s0 + (int)s1 + (int)s2 + (int)s3;
        if (s0 | s1 | s2 | s3) {
            if (s0) ssum += __fdividef(1.f, 1.f + __expf(-x[k].x));
            if (s1) ssum += __fdividef(1.f, 1.f + __expf(-x[k].y));
            if (s2) ssum += __fdividef(1.f, 1.f + __expf(-x[k].z));
            if (s3) ssum += __fdividef(1.f, 1.f + __expf(-x[k].w));
        }
    }

    // Deterministic fixed-point conversion before reduction
    unsigned long long fsum = (unsigned long long)(ssum * FIXSCALE + 0.5f);

    // Block reduction (8 warps)
    __shared__ int                scnt[8];
    __shared__ unsigned long long ssh[8];
    #pragma unroll
    for (int off = 16; off > 0; off >>= 1) {
        cnt  += __shfl_down_sync(0xFFFFFFFFu, cnt,  off);
        fsum += __shfl_down_sync(0xFFFFFFFFu, fsum, off);
    }
    int wid  = threadIdx.x >> 5;
    int lane = threadIdx.x & 31;
    if (lane == 0) { scnt[wid] = cnt; ssh[wid] = fsum; }
    __syncthreads();
    if (threadIdx.x == 0) {
        int tc = 0; unsigned long long ts = 0ULL;
        #pragma unroll
        for (int w = 0; w < 8; w++) { tc += scnt[w]; ts += ssh[w]; }
        atomicAdd(&g_cnt[bq], tc);
        atomicAdd(&g_ssum[bq], ts);
    }
}

// ---------------------------------------------------------------------------
// Kernel 2: grid (S_, BQ_). Emit score/valid; re-zero the (rare) rows that
// have cls>=4 but cnt<50; fg_idxs -> global_ids float spread across blocks.
// Then restore the scratch counters to zero for the next graph replay via a
// per-row arrival counter: every block reads its row's accumulators FIRST,
// fences, arrives; the last arrival resets. Deterministic (integer atomics,
// same final state regardless of arrival order).
// ---------------------------------------------------------------------------
__global__ __launch_bounds__(256)
void finalize_kernel(const int* __restrict__ fg_idxs,
                     float* __restrict__ out_masks,
                     float* __restrict__ out_scores,
                     float* __restrict__ out_valid,
                     float* __restrict__ out_gid)
{
    const int chunk = blockIdx.x;
    const int bq    = blockIdx.y;

    // gid convert: flatten block space over 200000 elements
    int gi = (bq * S_ + chunk) * 256 + threadIdx.x;
    if (gi < BN_) out_gid[gi] = (float)fg_idxs[gi];

    const int cls = g_cls_pred[bq];
    const int cnt = g_cnt[bq];
    const unsigned long long fs = g_ssum[bq];
    const int v   = (cnt >= MIN_PTS_NUM) && (cls >= MIN_INST_CLS);

    if (chunk == 0 && threadIdx.x == 0) {
        out_valid[bq] = (float)v;
        float sum = (float)((double)fs * (1.0 / 16777216.0));
        out_scores[bq] = v ? sum / (float)cnt : 0.f;
    }

    if (!v && cls >= MIN_INST_CLS) {   // rare: instance class but too few points
        float4* __restrict__ om = reinterpret_cast<float4*>(out_masks) +
                                  (size_t)bq * NV_ + (size_t)chunk * CHUNK_;
        const float4 z = make_float4(0.f, 0.f, 0.f, 0.f);
        #pragma unroll
        for (int k = 0; k < 5; k++) {
            int i = threadIdx.x + k * 256;
            if (i < CHUNK_) __stcs(&om[i], z);
        }
    }

    // Scratch reset: last block of this row (after all have read) zeroes it.
    __syncthreads();
    if (threadIdx.x == 0) {
        __threadfence();
        int prev = atomicAdd(&g_done[bq], 1);
        if (prev == S_ - 1) {
            g_cnt[bq]  = 0;
            g_ssum[bq] = 0ULL;
            g_done[bq] = 0;
            __threadfence();
        }
    }
}

// ---------------------------------------------------------------------------
extern "C" void kernel_launch(void* const* d_in, const int* in_sizes, int n_in,
                              void* d_out, int out_size)
{
    const float* mask_logits = (const float*)d_in[0];   // [B,Q,N]  fp32
    const float* cls_logits  = (const float*)d_in[1];   // [B,Q,C]  fp32
    const int*   seg_pred    = (const int*)d_in[2];     // [B,N]    int32
    const int*   fg_idxs     = (const int*)d_in[3];     // [B*N]    int32
    float* out = (float*)d_out;

    float* out_masks  = out;
    float* out_scores = out + OFF_SCORES;
    float* out_valid  = out + OFF_VALID;
    float* out_cls    = out + OFF_CLS;
    float* out_gid    = out + OFF_GID;

    dim3 grid2(S_, BQ_);
    mask_chunk_kernel<<<grid2, 256>>>(mask_logits, cls_logits, seg_pred,
                                      out_masks, out_cls);
    finalize_kernel<<<grid2, 256>>>(fg_idxs, out_masks, out_scores,
                                    out_valid, out_gid);
}

// round 6
// speedup vs baseline: 1.0071x; 1.0071x over previous
#include <cuda_runtime.h>

// Problem shapes (fixed for this dataset entry)
#define B_   4
#define Q_   128
#define N_   50000
#define C_   20
#define BQ_  (B_ * Q_)          // 512
#define BN_  (B_ * N_)          // 200000
#define NV_  (N_ / 4)           // 12500 float4 per row
#define S_   10                 // chunks per row
#define CHUNK_ (NV_ / S_)       // 1250 float4 per chunk

#define MIN_PTS_NUM  50
#define MIN_INST_CLS 4

// Output layout (fp32 concatenation, matching reference return order)
#define OFF_SCORES ((size_t)BQ_ * N_)            // 25,600,000
#define OFF_VALID  (OFF_SCORES + BQ_)
#define OFF_CLS    (OFF_VALID + BQ_)
#define OFF_GID    (OFF_CLS + BQ_)

// Scratch (no device allocation -> __device__ globals). Written by plain
// overwriting stores every invocation -> idempotent across graph replays,
// no reset, no atomics, no fences.
__device__ int   g_part_cnt[BQ_][S_];
__device__ float g_part_sum[BQ_][S_];

// Inline per-row argmax over C=20 class logits. All threads of the block read
// the same addresses -> uniform broadcast loads (L2-hit after first block of
// the row). Matches jnp.argmax first-max semantics.
__device__ __forceinline__ int row_argmax(const float* __restrict__ p)
{
    float best = __ldg(&p[0]);
    int bi = 0;
    #pragma unroll
    for (int c = 1; c < C_; c++) {
        float v = __ldg(&p[c]);
        if (v > best) { best = v; bi = c; }
    }
    return bi;
}

// ---------------------------------------------------------------------------
// Kernel 1: grid (S_, BQ_). One block per 1250-float4 chunk of one (b,q) row.
// Computes its row's class argmax inline. cls<4 rows are invalid regardless
// of count -> stream zeros, no logit read. Otherwise:
// sel = (logit>0) & (seg==cls)  [sigmoid(x)>0.5 <=> x>0, no MUFU for select];
// write mask (streaming), block-reduce (count, sigmoid sum over selected),
// plain-store the partials into the per-(row,chunk) slot.
// ---------------------------------------------------------------------------
__global__ __launch_bounds__(256)
void mask_chunk_kernel(const float* __restrict__ mask_logits,
                       const float* __restrict__ cls_logits,
                       const int* __restrict__ seg_pred,
                       float* __restrict__ out_masks,
                       float* __restrict__ out_cls)
{
    const int chunk = blockIdx.x;
    const int bq    = blockIdx.y;
    const int b     = bq >> 7;            // / Q_
    const int cls   = row_argmax(cls_logits + bq * C_);
    const size_t base = (size_t)bq * NV_ + (size_t)chunk * CHUNK_;

    if (chunk == 0 && threadIdx.x == 0)
        out_cls[bq] = (float)cls;

    float4* __restrict__ om = reinterpret_cast<float4*>(out_masks) + base;

    if (cls < MIN_INST_CLS) {
        const float4 z = make_float4(0.f, 0.f, 0.f, 0.f);
        #pragma unroll
        for (int k = 0; k < 5; k++) {
            int i = threadIdx.x + k * 256;
            if (i < CHUNK_) __stcs(&om[i], z);
        }
        if (threadIdx.x == 0) {           // still publish partials (zero)
            g_part_cnt[bq][chunk] = 0;
            g_part_sum[bq][chunk] = 0.f;
        }
        return;
    }

    const float4* __restrict__ ml = reinterpret_cast<const float4*>(mask_logits) + base;
    const int4*   __restrict__ sp = reinterpret_cast<const int4*>(seg_pred) +
                                    (size_t)b * NV_ + (size_t)chunk * CHUNK_;

    int   cnt  = 0;
    float ssum = 0.f;

    // Fully unrolled: 5 independent (float4, int4) load pairs batched up
    // front for MLP, then compute+store.
    float4 x[5]; int4 s[5]; bool ok[5];
    #pragma unroll
    for (int k = 0; k < 5; k++) {
        int i = threadIdx.x + k * 256;
        ok[k] = (i < CHUNK_);
        if (ok[k]) { x[k] = __ldcs(&ml[i]); s[k] = __ldg(&sp[i]); }
    }
    #pragma unroll
    for (int k = 0; k < 5; k++) {
        if (!ok[k]) continue;
        int i = threadIdx.x + k * 256;
        bool s0 = (x[k].x > 0.f) & (s[k].x == cls);
        bool s1 = (x[k].y > 0.f) & (s[k].y == cls);
        bool s2 = (x[k].z > 0.f) & (s[k].z == cls);
        bool s3 = (x[k].w > 0.f) & (s[k].w == cls);
        float4 o;
        o.x = s0 ? 1.f : 0.f;
        o.y = s1 ? 1.f : 0.f;
        o.z = s2 ? 1.f : 0.f;
        o.w = s3 ? 1.f : 0.f;
        __stcs(&om[i], o);
        cnt += (int)s0 + (int)s1 + (int)s2 + (int)s3;
        if (s0 | s1 | s2 | s3) {
            if (s0) ssum += __fdividef(1.f, 1.f + __expf(-x[k].x));
            if (s1) ssum += __fdividef(1.f, 1.f + __expf(-x[k].y));
            if (s2) ssum += __fdividef(1.f, 1.f + __expf(-x[k].z));
            if (s3) ssum += __fdividef(1.f, 1.f + __expf(-x[k].w));
        }
    }

    // Block reduction (8 warps); fixed shuffle-tree order -> deterministic.
    __shared__ int   scnt[8];
    __shared__ float ssh[8];
    #pragma unroll
    for (int off = 16; off > 0; off >>= 1) {
        cnt  += __shfl_down_sync(0xFFFFFFFFu, cnt,  off);
        ssum += __shfl_down_sync(0xFFFFFFFFu, ssum, off);
    }
    int wid  = threadIdx.x >> 5;
    int lane = threadIdx.x & 31;
    if (lane == 0) { scnt[wid] = cnt; ssh[wid] = ssum; }
    __syncthreads();
    if (threadIdx.x == 0) {
        int tc = 0; float ts = 0.f;
        #pragma unroll
        for (int w = 0; w < 8; w++) { tc += scnt[w]; ts += ssh[w]; }
        g_part_cnt[bq][chunk] = tc;     // plain store, no reset needed
        g_part_sum[bq][chunk] = ts;
    }
}

// ---------------------------------------------------------------------------
// Kernel 2: grid (S_, BQ_). Sum the 10 partials (fixed order, deterministic,
// broadcast loads), emit score/valid (chunk 0 only), re-zero the rare rows
// with cls>=4 but cnt<50, and convert fg_idxs -> global_ids float. No
// atomics, no fences, no scratch mutation beyond idempotent next-run stores.
// ---------------------------------------------------------------------------
__global__ __launch_bounds__(256)
void finalize_kernel(const float* __restrict__ cls_logits,
                     const int* __restrict__ fg_idxs,
                     float* __restrict__ out_masks,
                     float* __restrict__ out_scores,
                     float* __restrict__ out_valid,
                     float* __restrict__ out_gid)
{
    const int chunk = blockIdx.x;
    const int bq    = blockIdx.y;

    // gid convert: flatten block space over 200000 elements
    int gi = (bq * S_ + chunk) * 256 + threadIdx.x;
    if (gi < BN_) out_gid[gi] = (float)fg_idxs[gi];

    // Total count/sum for this row: 10 broadcast loads, fixed order.
    int   cnt = 0;
    float sum = 0.f;
    #pragma unroll
    for (int c = 0; c < S_; c++) {
        cnt += g_part_cnt[bq][c];
        sum += g_part_sum[bq][c];
    }
    const int cls = row_argmax(cls_logits + bq * C_);
    const int v   = (cnt >= MIN_PTS_NUM) && (cls >= MIN_INST_CLS);

    if (chunk == 0 && threadIdx.x == 0) {
        out_valid[bq]  = (float)v;
        out_scores[bq] = v ? sum / (float)cnt : 0.f;
    }

    if (!v && cls >= MIN_INST_CLS) {   // rare: instance class but too few points
        float4* __restrict__ om = reinterpret_cast<float4*>(out_masks) +
                                  (size_t)bq * NV_ + (size_t)chunk * CHUNK_;
        const float4 z = make_float4(0.f, 0.f, 0.f, 0.f);
        #pragma unroll
        for (int k = 0; k < 5; k++) {
            int i = threadIdx.x + k * 256;
            if (i < CHUNK_) __stcs(&om[i], z);
        }
    }
}

// ---------------------------------------------------------------------------
extern "C" void kernel_launch(void* const* d_in, const int* in_sizes, int n_in,
                              void* d_out, int out_size)
{
    const float* mask_logits = (const float*)d_in[0];   // [B,Q,N]  fp32
    const float* cls_logits  = (const float*)d_in[1];   // [B,Q,C]  fp32
    const int*   seg_pred    = (const int*)d_in[2];     // [B,N]    int32
    const int*   fg_idxs     = (const int*)d_in[3];     // [B*N]    int32
    float* out = (float*)d_out;

    float* out_masks  = out;
    float* out_scores = out + OFF_SCORES;
    float* out_valid  = out + OFF_VALID;
    float* out_cls    = out + OFF_CLS;
    float* out_gid    = out + OFF_GID;

    dim3 grid2(S_, BQ_);
    mask_chunk_kernel<<<grid2, 256>>>(mask_logits, cls_logits, seg_pred,
                                      out_masks, out_cls);
    finalize_kernel<<<grid2, 256>>>(cls_logits, fg_idxs, out_masks,
                                    out_scores, out_valid, out_gid);
}

// round 7
// speedup vs baseline: 1.1453x; 1.1372x over previous
#include <cuda_runtime.h>

// Problem shapes (fixed for this dataset entry)
#define B_   4
#define Q_   128
#define N_   50000
#define C_   20
#define BQ_  (B_ * Q_)          // 512
#define BN_  (B_ * N_)          // 200000
#define NV_  (N_ / 4)           // 12500 float4 per row
#define S_   10                 // chunks per row
#define CHUNK_ (NV_ / S_)       // 1250 float4 per chunk

#define MIN_PTS_NUM  50
#define MIN_INST_CLS 4

// Output layout (fp32 concatenation, matching reference return order)
#define OFF_SCORES ((size_t)BQ_ * N_)            // 25,600,000
#define OFF_VALID  (OFF_SCORES + BQ_)
#define OFF_CLS    (OFF_VALID + BQ_)
#define OFF_GID    (OFF_CLS + BQ_)

// Scratch (no device allocation -> __device__ globals). Written by plain
// overwriting stores every invocation -> idempotent across graph replays,
// no reset, no atomics, no fences.
__device__ int   g_part_cnt[BQ_][S_];
__device__ float g_part_sum[BQ_][S_];
__device__ int   g_needzero[BQ_];

// Inline per-row argmax over C=20 class logits. Matches jnp.argmax first-max.
__device__ __forceinline__ int row_argmax(const float* __restrict__ p)
{
    float best = __ldg(&p[0]);
    int bi = 0;
    #pragma unroll
    for (int c = 1; c < C_; c++) {
        float v = __ldg(&p[c]);
        if (v > best) { best = v; bi = c; }
    }
    return bi;
}

// ---------------------------------------------------------------------------
// Kernel 1: grid (S_, BQ_). One block per 1250-float4 chunk of one (b,q) row.
// Computes its row's class argmax inline (broadcast loads, L2-hot). cls<4
// rows are invalid regardless of count -> stream zeros, no logit read.
// Otherwise: sel = (logit>0) & (seg==cls)  [sigmoid(x)>0.5 <=> x>0 -> no
// MUFU for selection]; write mask (streaming), block-reduce (count, sigmoid
// sum over selected), plain-store partials into the per-(row,chunk) slot.
// ---------------------------------------------------------------------------
__global__ __launch_bounds__(256)
void mask_chunk_kernel(const float* __restrict__ mask_logits,
                       const float* __restrict__ cls_logits,
                       const int* __restrict__ seg_pred,
                       float* __restrict__ out_masks)
{
    const int chunk = blockIdx.x;
    const int bq    = blockIdx.y;
    const int b     = bq >> 7;            // / Q_
    const int cls   = row_argmax(cls_logits + bq * C_);
    const size_t base = (size_t)bq * NV_ + (size_t)chunk * CHUNK_;

    float4* __restrict__ om = reinterpret_cast<float4*>(out_masks) + base;

    if (cls < MIN_INST_CLS) {
        const float4 z = make_float4(0.f, 0.f, 0.f, 0.f);
        #pragma unroll
        for (int k = 0; k < 5; k++) {
            int i = threadIdx.x + k * 256;
            if (i < CHUNK_) __stcs(&om[i], z);
        }
        if (threadIdx.x == 0) {           // still publish partials (zero)
            g_part_cnt[bq][chunk] = 0;
            g_part_sum[bq][chunk] = 0.f;
        }
        return;
    }

    const float4* __restrict__ ml = reinterpret_cast<const float4*>(mask_logits) + base;
    const int4*   __restrict__ sp = reinterpret_cast<const int4*>(seg_pred) +
                                    (size_t)b * NV_ + (size_t)chunk * CHUNK_;

    int   cnt  = 0;
    float ssum = 0.f;

    // Fully unrolled: 5 independent (float4, int4) load pairs batched up
    // front for MLP, then compute+store.
    float4 x[5]; int4 s[5]; bool ok[5];
    #pragma unroll
    for (int k = 0; k < 5; k++) {
        int i = threadIdx.x + k * 256;
        ok[k] = (i < CHUNK_);
        if (ok[k]) { x[k] = __ldcs(&ml[i]); s[k] = __ldg(&sp[i]); }
    }
    #pragma unroll
    for (int k = 0; k < 5; k++) {
        if (!ok[k]) continue;
        int i = threadIdx.x + k * 256;
        bool s0 = (x[k].x > 0.f) & (s[k].x == cls);
        bool s1 = (x[k].y > 0.f) & (s[k].y == cls);
        bool s2 = (x[k].z > 0.f) & (s[k].z == cls);
        bool s3 = (x[k].w > 0.f) & (s[k].w == cls);
        float4 o;
        o.x = s0 ? 1.f : 0.f;
        o.y = s1 ? 1.f : 0.f;
        o.z = s2 ? 1.f : 0.f;
        o.w = s3 ? 1.f : 0.f;
        __stcs(&om[i], o);
        cnt += (int)s0 + (int)s1 + (int)s2 + (int)s3;
        if (s0 | s1 | s2 | s3) {
            if (s0) ssum += __fdividef(1.f, 1.f + __expf(-x[k].x));
            if (s1) ssum += __fdividef(1.f, 1.f + __expf(-x[k].y));
            if (s2) ssum += __fdividef(1.f, 1.f + __expf(-x[k].z));
            if (s3) ssum += __fdividef(1.f, 1.f + __expf(-x[k].w));
        }
    }

    // Block reduction (8 warps); fixed shuffle-tree order -> deterministic.
    __shared__ int   scnt[8];
    __shared__ float ssh[8];
    #pragma unroll
    for (int off = 16; off > 0; off >>= 1) {
        cnt  += __shfl_down_sync(0xFFFFFFFFu, cnt,  off);
        ssum += __shfl_down_sync(0xFFFFFFFFu, ssum, off);
    }
    int wid  = threadIdx.x >> 5;
    int lane = threadIdx.x & 31;
    if (lane == 0) { scnt[wid] = cnt; ssh[wid] = ssum; }
    __syncthreads();
    if (threadIdx.x == 0) {
        int tc = 0; float ts = 0.f;
        #pragma unroll
        for (int w = 0; w < 8; w++) { tc += scnt[w]; ts += ssh[w]; }
        g_part_cnt[bq][chunk] = tc;     // plain store, no reset needed
        g_part_sum[bq][chunk] = ts;
    }
}

// ---------------------------------------------------------------------------
// Kernel 2 (small): 782 blocks. Per-thread gid convert (the only bulk work,
// 1.6 MB). ONLY the first 512 global threads do the per-row epilogue: sum 10
// partials in fixed order (deterministic), argmax, write score/valid/cls and
// the needzero flag. Redundant work: ~16K loads total instead of 40M.
// ---------------------------------------------------------------------------
__global__ __launch_bounds__(256)
void finalize_small_kernel(const float* __restrict__ cls_logits,
                           const int* __restrict__ fg_idxs,
                           float* __restrict__ out_scores,
                           float* __restrict__ out_valid,
                           float* __restrict__ out_cls,
                           float* __restrict__ out_gid)
{
    int gi = blockIdx.x * 256 + threadIdx.x;
    if (gi < BN_) out_gid[gi] = (float)fg_idxs[gi];

    if (gi < BQ_) {
        const int bq = gi;
        int   cnt = 0;
        float sum = 0.f;
        #pragma unroll
        for (int c = 0; c < S_; c++) {
            cnt += g_part_cnt[bq][c];
            sum += g_part_sum[bq][c];
        }
        const int cls = row_argmax(cls_logits + bq * C_);
        const int v   = (cnt >= MIN_PTS_NUM) && (cls >= MIN_INST_CLS);
        out_cls[bq]    = (float)cls;
        out_valid[bq]  = (float)v;
        out_scores[bq] = v ? sum / (float)cnt : 0.f;
        // Re-zero needed only when an instance-class row misses the count
        // threshold (cls<4 rows were zero-streamed already in K1).
        g_needzero[bq] = (!v) && (cls >= MIN_INST_CLS);
    }
}

// ---------------------------------------------------------------------------
// Kernel 3: 512 blocks, one per row. Broadcast flag load; almost always exits
// immediately. If flagged (instance class but <50 points), zero the row.
// ---------------------------------------------------------------------------
__global__ __launch_bounds__(256)
void zero_invalid_kernel(float* __restrict__ out_masks)
{
    const int bq = blockIdx.x;
    if (!g_needzero[bq]) return;
    float4* __restrict__ om = reinterpret_cast<float4*>(out_masks) + (size_t)bq * NV_;
    const float4 z = make_float4(0.f, 0.f, 0.f, 0.f);
    for (int i = threadIdx.x; i < NV_; i += 256)
        __stcs(&om[i], z);
}

// ---------------------------------------------------------------------------
extern "C" void kernel_launch(void* const* d_in, const int* in_sizes, int n_in,
                              void* d_out, int out_size)
{
    const float* mask_logits = (const float*)d_in[0];   // [B,Q,N]  fp32
    const float* cls_logits  = (const float*)d_in[1];   // [B,Q,C]  fp32
    const int*   seg_pred    = (const int*)d_in[2];     // [B,N]    int32
    const int*   fg_idxs     = (const int*)d_in[3];     // [B*N]    int32
    float* out = (float*)d_out;

    float* out_masks  = out;
    float* out_scores = out + OFF_SCORES;
    float* out_valid  = out + OFF_VALID;
    float* out_cls    = out + OFF_CLS;
    float* out_gid    = out + OFF_GID;

    dim3 grid2(S_, BQ_);
    mask_chunk_kernel<<<grid2, 256>>>(mask_logits, cls_logits, seg_pred,
                                      out_masks);
    finalize_small_kernel<<<(BN_ + 255) / 256, 256>>>(cls_logits, fg_idxs,
                                                      out_scores, out_valid,
                                                      out_cls, out_gid);
    zero_invalid_kernel<<<BQ_, 256>>>(out_masks);
}

// round 8
// speedup vs baseline: 1.2080x; 1.0548x over previous
#include <cuda_runtime.h>

// Problem shapes (fixed for this dataset entry)
#define B_   4
#define Q_   128
#define N_   50000
#define C_   20
#define BQ_  (B_ * Q_)          // 512
#define BN_  (B_ * N_)          // 200000
#define NV_  (N_ / 4)           // 12500 float4 per row
#define S_   10                 // chunks per row
#define CHUNK_ (NV_ / S_)       // 1250 float4 per chunk

#define MIN_PTS_NUM  50
#define MIN_INST_CLS 4

// Output layout (fp32 concatenation, matching reference return order)
#define OFF_SCORES ((size_t)BQ_ * N_)            // 25,600,000
#define OFF_VALID  (OFF_SCORES + BQ_)
#define OFF_CLS    (OFF_VALID + BQ_)
#define OFF_GID    (OFF_CLS + BQ_)

// Scratch (no device allocation -> __device__ globals). Written by plain
// overwriting stores every invocation -> idempotent across graph replays,
// no reset, no atomics, no fences.
__device__ int   g_part_cnt[BQ_][S_];
__device__ float g_part_sum[BQ_][S_];

// Inline per-row argmax over C=20 class logits. Matches jnp.argmax first-max.
__device__ __forceinline__ int row_argmax(const float* __restrict__ p)
{
    float best = __ldg(&p[0]);
    int bi = 0;
    #pragma unroll
    for (int c = 1; c < C_; c++) {
        float v = __ldg(&p[c]);
        if (v > best) { best = v; bi = c; }
    }
    return bi;
}

// ---------------------------------------------------------------------------
// Kernel 1: grid (S_, BQ_). One block per 1250-float4 chunk of one (b,q) row.
// __launch_bounds__(256, 6): cap regs at 40 -> 6 blocks/SM -> occ ~75%
// (was 48 regs / 5 blocks / 55%, leaving DRAM at 52%).
// Computes its row's class argmax inline (broadcast loads, L2-hot). cls<4
// rows are invalid regardless of count -> stream zeros, no logit read.
// Otherwise: sel = (logit>0) & (seg==cls)  [sigmoid(x)>0.5 <=> x>0 -> no
// MUFU for selection]; write mask (streaming), block-reduce (count, sigmoid
// sum over selected), plain-store partials into the per-(row,chunk) slot.
// ---------------------------------------------------------------------------
__global__ __launch_bounds__(256, 6)
void mask_chunk_kernel(const float* __restrict__ mask_logits,
                       const float* __restrict__ cls_logits,
                       const int* __restrict__ seg_pred,
                       float* __restrict__ out_masks)
{
    const int chunk = blockIdx.x;
    const int bq    = blockIdx.y;
    const int b     = bq >> 7;            // / Q_
    const int cls   = row_argmax(cls_logits + bq * C_);
    const size_t base = (size_t)bq * NV_ + (size_t)chunk * CHUNK_;

    float4* __restrict__ om = reinterpret_cast<float4*>(out_masks) + base;

    if (cls < MIN_INST_CLS) {
        const float4 z = make_float4(0.f, 0.f, 0.f, 0.f);
        #pragma unroll
        for (int k = 0; k < 5; k++) {
            int i = threadIdx.x + k * 256;
            if (i < CHUNK_) __stcs(&om[i], z);
        }
        if (threadIdx.x == 0) {           // still publish partials (zero)
            g_part_cnt[bq][chunk] = 0;
            g_part_sum[bq][chunk] = 0.f;
        }
        return;
    }

    const float4* __restrict__ ml = reinterpret_cast<const float4*>(mask_logits) + base;
    const int4*   __restrict__ sp = reinterpret_cast<const int4*>(seg_pred) +
                                    (size_t)b * NV_ + (size_t)chunk * CHUNK_;

    int   cnt  = 0;
    float ssum = 0.f;

    // 5 (float4, int4) pairs; k<4 bounds are compile-time true (1024<1250),
    // only k=4 is predicated. Reg cap lets ptxas choose pipeline depth.
    float4 x[5]; int4 s[5];
    #pragma unroll
    for (int k = 0; k < 5; k++) {
        int i = threadIdx.x + k * 256;
        if (k < 4 || i < CHUNK_) { x[k] = __ldcs(&ml[i]); s[k] = __ldg(&sp[i]); }
    }
    #pragma unroll
    for (int k = 0; k < 5; k++) {
        int i = threadIdx.x + k * 256;
        if (k == 4 && i >= CHUNK_) continue;
        bool s0 = (x[k].x > 0.f) & (s[k].x == cls);
        bool s1 = (x[k].y > 0.f) & (s[k].y == cls);
        bool s2 = (x[k].z > 0.f) & (s[k].z == cls);
        bool s3 = (x[k].w > 0.f) & (s[k].w == cls);
        float4 o;
        o.x = s0 ? 1.f : 0.f;
        o.y = s1 ? 1.f : 0.f;
        o.z = s2 ? 1.f : 0.f;
        o.w = s3 ? 1.f : 0.f;
        __stcs(&om[i], o);
        cnt += (int)s0 + (int)s1 + (int)s2 + (int)s3;
        if (s0 | s1 | s2 | s3) {
            if (s0) ssum += __fdividef(1.f, 1.f + __expf(-x[k].x));
            if (s1) ssum += __fdividef(1.f, 1.f + __expf(-x[k].y));
            if (s2) ssum += __fdividef(1.f, 1.f + __expf(-x[k].z));
            if (s3) ssum += __fdividef(1.f, 1.f + __expf(-x[k].w));
        }
    }

    // Block reduction (8 warps); fixed shuffle-tree order -> deterministic.
    __shared__ int   scnt[8];
    __shared__ float ssh[8];
    #pragma unroll
    for (int off = 16; off > 0; off >>= 1) {
        cnt  += __shfl_down_sync(0xFFFFFFFFu, cnt,  off);
        ssum += __shfl_down_sync(0xFFFFFFFFu, ssum, off);
    }
    int wid  = threadIdx.x >> 5;
    int lane = threadIdx.x & 31;
    if (lane == 0) { scnt[wid] = cnt; ssh[wid] = ssum; }
    __syncthreads();
    if (threadIdx.x == 0) {
        int tc = 0; float ts = 0.f;
        #pragma unroll
        for (int w = 0; w < 8; w++) { tc += scnt[w]; ts += ssh[w]; }
        g_part_cnt[bq][chunk] = tc;     // plain store, no reset needed
        g_part_sum[bq][chunk] = ts;
    }
}

// ---------------------------------------------------------------------------
// Kernel 2 (fused epilogue): 782 blocks.
//  - every thread: one gid convert (the only bulk traffic, 1.6 MB)
//  - blocks 0..511 (block == row bq): thread 0 sums the 10 partials in fixed
//    order (deterministic), argmax, writes score/valid/cls, raises a smem
//    flag if the row needs re-zero (instance class but cnt<50 -- with this
//    data distribution cnt~1250, 34 sigma above 50, so the zero path is a
//    never-executed safety net); whole block zeroes the row iff flagged.
// ---------------------------------------------------------------------------
__global__ __launch_bounds__(256)
void finalize_kernel(const float* __restrict__ cls_logits,
                     const int* __restrict__ fg_idxs,
                     float* __restrict__ out_masks,
                     float* __restrict__ out_scores,
                     float* __restrict__ out_valid,
                     float* __restrict__ out_cls,
                     float* __restrict__ out_gid)
{
    int gi = blockIdx.x * 256 + threadIdx.x;
    if (gi < BN_) out_gid[gi] = (float)fg_idxs[gi];

    const int bq = blockIdx.x;
    if (bq >= BQ_) return;                // whole-block uniform exit

    __shared__ int flag;
    if (threadIdx.x == 0) {
        int   cnt = 0;
        float sum = 0.f;
        #pragma unroll
        for (int c = 0; c < S_; c++) {
            cnt += g_part_cnt[bq][c];
            sum += g_part_sum[bq][c];
        }
        const int cls = row_argmax(cls_logits + bq * C_);
        const int v   = (cnt >= MIN_PTS_NUM) && (cls >= MIN_INST_CLS);
        out_cls[bq]    = (float)cls;
        out_valid[bq]  = (float)v;
        out_scores[bq] = v ? sum / (float)cnt : 0.f;
        flag = (!v) && (cls >= MIN_INST_CLS);
    }
    __syncthreads();

    if (flag) {                            // rare/never: slow path is fine
        float4* __restrict__ om = reinterpret_cast<float4*>(out_masks) + (size_t)bq * NV_;
        const float4 z = make_float4(0.f, 0.f, 0.f, 0.f);
        for (int i = threadIdx.x; i < NV_; i += 256)
            __stcs(&om[i], z);
    }
}

// ---------------------------------------------------------------------------
extern "C" void kernel_launch(void* const* d_in, const int* in_sizes, int n_in,
                              void* d_out, int out_size)
{
    const float* mask_logits = (const float*)d_in[0];   // [B,Q,N]  fp32
    const float* cls_logits  = (const float*)d_in[1];   // [B,Q,C]  fp32
    const int*   seg_pred    = (const int*)d_in[2];     // [B,N]    int32
    const int*   fg_idxs     = (const int*)d_in[3];     // [B*N]    int32
    float* out = (float*)d_out;

    float* out_masks  = out;
    float* out_scores = out + OFF_SCORES;
    float* out_valid  = out + OFF_VALID;
    float* out_cls    = out + OFF_CLS;
    float* out_gid    = out + OFF_GID;

    dim3 grid2(S_, BQ_);
    mask_chunk_kernel<<<grid2, 256>>>(mask_logits, cls_logits, seg_pred,
                                      out_masks);
    finalize_kernel<<<(BN_ + 255) / 256, 256>>>(cls_logits, fg_idxs, out_masks,
                                                out_scores, out_valid,
                                                out_cls, out_gid);
}